// round 10
// baseline (speedup 1.0000x reference)
#include <cuda_runtime.h>
#include <cuda_bf16.h>
#include <cstdint>

#define BSZ   512
#define NNODE 22
#define INDIM 128
#define HID   256
#define MROWS (BSZ * NNODE)   // 11264

// Scratch (device globals) — activations & weights stored pre-split (bf16 hi/lo)
__device__ __nv_bfloat16 g_hsh[BSZ * HID], g_hsl[BSZ * HID];
__device__ __nv_bfloat16 g_Wth[3 * HID * HID], g_Wtl[3 * HID * HID]; // [n][k]

// ---------------------------------------------------------------------------
// bf16 split-2 helpers
// ---------------------------------------------------------------------------
__device__ __forceinline__ void bf16_split2(float v0, float v1,
                                            uint32_t& hi, uint32_t& lo) {
    __nv_bfloat162 h = __float22bfloat162_rn(make_float2(v0, v1));
    float2 hf = __bfloat1622float2(h);
    __nv_bfloat162 l = __float22bfloat162_rn(make_float2(v0 - hf.x, v1 - hf.y));
    hi = *reinterpret_cast<uint32_t*>(&h);
    lo = *reinterpret_cast<uint32_t*>(&l);
}

__device__ __forceinline__ void split1(float v, __nv_bfloat16& h, __nv_bfloat16& l) {
    h = __float2bfloat16_rn(v);
    l = __float2bfloat16_rn(v - __bfloat162float(h));
}

__device__ __forceinline__ void mma_bf16(float* d, const uint32_t* a,
                                         uint32_t b0, uint32_t b1) {
    asm volatile(
        "mma.sync.aligned.m16n8k16.row.col.f32.bf16.bf16.f32 "
        "{%0,%1,%2,%3}, {%4,%5,%6,%7}, {%8,%9}, {%0,%1,%2,%3};"
        : "+f"(d[0]), "+f"(d[1]), "+f"(d[2]), "+f"(d[3])
        : "r"(a[0]), "r"(a[1]), "r"(a[2]), "r"(a[3]), "r"(b0), "r"(b1));
}

__device__ __forceinline__ uint32_t lds_u32(const __nv_bfloat16* p) {
    return *reinterpret_cast<const uint32_t*>(p);
}
__device__ __forceinline__ uint32_t ldg_u32(const __nv_bfloat16* p) {
    return *reinterpret_cast<const uint32_t*>(p);
}

// ---------------------------------------------------------------------------
// K1: h = relu(x @ (We1[:128]+We1[128:]) + be1), fused 22-row segment reduce.
// (unchanged) grid (4, 64+3); y>=64 -> weight transpose+split role.
// ---------------------------------------------------------------------------
__global__ __launch_bounds__(256)
void k1_mma(const float* __restrict__ x,
            const float* __restrict__ We1,
            const float* __restrict__ be1,
            const float* __restrict__ We2,
            const float* __restrict__ Wn1,
            const float* __restrict__ Wn2) {
    if (blockIdx.y >= 64) {
        const int mat = blockIdx.y - 64;
        const float* Wsrc = (mat == 0) ? We2 : (mat == 1) ? Wn1 : Wn2;
        __nv_bfloat16* dh = g_Wth + mat * HID * HID;
        __nv_bfloat16* dl = g_Wtl + mat * HID * HID;
        const int k0 = blockIdx.x * 64;
        const int n  = threadIdx.x;
        for (int kq = 0; kq < 64; kq += 4) {
            __nv_bfloat16 h[4], l[4];
#pragma unroll
            for (int i = 0; i < 4; i++)
                split1(Wsrc[(size_t)(k0 + kq + i) * HID + n], h[i], l[i]);
            *(uint2*)&dh[(size_t)n * HID + k0 + kq] = *(uint2*)h;
            *(uint2*)&dl[(size_t)n * HID + k0 + kq] = *(uint2*)l;
        }
        return;
    }

    __shared__ __align__(16) unsigned char sm[176 * 68 * 4];
    __nv_bfloat16* Ah = (__nv_bfloat16*)sm;                    // [176][40]
    __nv_bfloat16* Al = (__nv_bfloat16*)(sm + 14080);
    __nv_bfloat16* Bh = (__nv_bfloat16*)(sm + 28160);          // [64][40]
    __nv_bfloat16* Bl = (__nv_bfloat16*)(sm + 33280);
    float* hb = (float*)sm;                                    // [176][68]

    const int t  = threadIdx.x;
    const int w  = t >> 5;
    const int l  = t & 31;
    const int g  = l >> 2;
    const int t4 = l & 3;
    const int n0 = blockIdx.x * 64;
    const int m0 = blockIdx.y * 176;

    float acc[11][4];
#pragma unroll
    for (int mt = 0; mt < 11; mt++)
#pragma unroll
        for (int j = 0; j < 4; j++) acc[mt][j] = 0.0f;

    for (int kc = 0; kc < 4; kc++) {
        const int k0 = kc * 32;
#pragma unroll
        for (int j = 0; j < 6; j++) {
            int flat = j * 256 + t;
            if (flat < 1408) {
                int m  = flat >> 3;
                int kq = (flat & 7) * 4;
                float4 v = *(const float4*)&x[(size_t)(m0 + m) * INDIM + k0 + kq];
                uint32_t h0, l0, h1, l1;
                bf16_split2(v.x, v.y, h0, l0);
                bf16_split2(v.z, v.w, h1, l1);
                *(uint32_t*)&Ah[m * 40 + kq]     = h0;
                *(uint32_t*)&Ah[m * 40 + kq + 2] = h1;
                *(uint32_t*)&Al[m * 40 + kq]     = l0;
                *(uint32_t*)&Al[m * 40 + kq + 2] = l1;
            }
        }
#pragma unroll
        for (int j = 0; j < 8; j++) {
            int flat = j * 256 + t;
            int kl = flat >> 6;
            int n  = flat & 63;
            float v = We1[(size_t)(k0 + kl) * HID + n0 + n]
                    + We1[(size_t)(k0 + kl + INDIM) * HID + n0 + n];
            split1(v, Bh[n * 40 + kl], Bl[n * 40 + kl]);
        }
        __syncthreads();

#pragma unroll
        for (int ks = 0; ks < 2; ks++) {
            const int kb = ks * 16 + 2 * t4;
            uint32_t bh0 = lds_u32(Bh + (8 * w + g) * 40 + kb);
            uint32_t bh1 = lds_u32(Bh + (8 * w + g) * 40 + kb + 8);
            uint32_t bl0 = lds_u32(Bl + (8 * w + g) * 40 + kb);
            uint32_t bl1 = lds_u32(Bl + (8 * w + g) * 40 + kb + 8);
#pragma unroll
            for (int mt = 0; mt < 11; mt++) {
                const int rb = mt * 16;
                uint32_t ah[4], al[4];
                ah[0] = lds_u32(Ah + (rb + g) * 40 + kb);
                ah[1] = lds_u32(Ah + (rb + g + 8) * 40 + kb);
                ah[2] = lds_u32(Ah + (rb + g) * 40 + kb + 8);
                ah[3] = lds_u32(Ah + (rb + g + 8) * 40 + kb + 8);
                al[0] = lds_u32(Al + (rb + g) * 40 + kb);
                al[1] = lds_u32(Al + (rb + g + 8) * 40 + kb);
                al[2] = lds_u32(Al + (rb + g) * 40 + kb + 8);
                al[3] = lds_u32(Al + (rb + g + 8) * 40 + kb + 8);
                mma_bf16(acc[mt], ah, bh0, bh1);
                mma_bf16(acc[mt], ah, bl0, bl1);
                mma_bf16(acc[mt], al, bh0, bh1);
            }
        }
        __syncthreads();
    }

    const int   cc  = 8 * w + 2 * t4;
    const float bv0 = be1[n0 + cc];
    const float bv1 = be1[n0 + cc + 1];
#pragma unroll
    for (int mt = 0; mt < 11; mt++) {
        const int r0 = mt * 16 + g;
        const int r1 = r0 + 8;
        hb[r0 * 68 + cc]     = fmaxf(acc[mt][0] + bv0, 0.0f);
        hb[r0 * 68 + cc + 1] = fmaxf(acc[mt][1] + bv1, 0.0f);
        hb[r1 * 68 + cc]     = fmaxf(acc[mt][2] + bv0, 0.0f);
        hb[r1 * 68 + cc + 1] = fmaxf(acc[mt][3] + bv1, 0.0f);
    }
    __syncthreads();

    {
        const int c = t & 63;
#pragma unroll
        for (int hh = 0; hh < 2; hh++) {
            const int gg = (t >> 6) + hh * 4;
            float s = 0.0f;
#pragma unroll
            for (int i = 0; i < 22; i++)
                s += hb[(gg * 22 + i) * 68 + c];
            size_t o = (size_t)(blockIdx.y * 8 + gg) * HID + n0 + c;
            split1(s, g_hsh[o], g_hsl[o]);
        }
    }
}

// ---------------------------------------------------------------------------
// Barrier-free fused tail: one block = 16 batch rows x FULL 256 cols.
// 8 warps; warp w owns cols [32w, 32w+32). Weights streamed global->registers
// (pre-split [n][k] layout -> coalesced 32B sectors). Activations live in a
// 16KB smem hi/lo buffer, re-split locally at each layer boundary.
// grid = 32 blocks, 256 threads. Zero global syncs.
// ---------------------------------------------------------------------------
__global__ __launch_bounds__(256)
void tail_ws(const float* __restrict__ be2,
             const float* __restrict__ bn1,
             const float* __restrict__ bn2,
             float* __restrict__ out) {
    __shared__ __align__(16) __nv_bfloat16 Ah[16 * 256];
    __shared__ __align__(16) __nv_bfloat16 Al[16 * 256];

    const int t  = threadIdx.x;
    const int w  = t >> 5;
    const int l  = t & 31;
    const int g  = l >> 2;
    const int t4 = l & 3;
    const int m0 = blockIdx.x * 16;
    const int nw = 32 * w;                 // this warp's column base

    // ---- stage L0 input (split hs) into smem: 2 uint4 per array/thread ----
#pragma unroll
    for (int j = 0; j < 2; j++) {
        int flat = j * 256 + t;            // uint4 index over [16][32]
        int m   = flat >> 5;
        int kq8 = (flat & 31) * 8;
        int kx  = kq8 ^ (8 * (m & 7));
        *(uint4*)&Ah[m * 256 + kx] = *(const uint4*)&g_hsh[(size_t)(m0 + m) * HID + kq8];
        *(uint4*)&Al[m * 256 + kx] = *(const uint4*)&g_hsl[(size_t)(m0 + m) * HID + kq8];
    }
    __syncthreads();

    const int swz = 8 * g;                 // rows g and g+8 share (row&7)==g

#pragma unroll 1
    for (int layer = 0; layer < 3; layer++) {
        const __nv_bfloat16* Wh = g_Wth + (size_t)layer * HID * HID;
        const __nv_bfloat16* Wl = g_Wtl + (size_t)layer * HID * HID;
        const float* bias = (layer == 0) ? be2 : (layer == 1) ? bn1 : bn2;
        const float bscale = (layer == 0) ? (float)NNODE : 1.0f;

        float acc[4][4];
#pragma unroll
        for (int nt = 0; nt < 4; nt++)
#pragma unroll
            for (int j = 0; j < 4; j++) acc[nt][j] = 0.0f;

        // full K=256 per warp: 16 k16-steps; B streamed from global
#pragma unroll
        for (int ks = 0; ks < 16; ks++) {
            const int kb  = 16 * ks;
            const int ka0 = (kb + 2 * t4) ^ swz;
            const int ka2 = (kb + 2 * t4 + 8) ^ swz;

            uint32_t ah[4], al[4];
            ah[0] = lds_u32(Ah + g * 256 + ka0);
            ah[1] = lds_u32(Ah + (g + 8) * 256 + ka0);
            ah[2] = lds_u32(Ah + g * 256 + ka2);
            ah[3] = lds_u32(Ah + (g + 8) * 256 + ka2);
            al[0] = lds_u32(Al + g * 256 + ka0);
            al[1] = lds_u32(Al + (g + 8) * 256 + ka0);
            al[2] = lds_u32(Al + g * 256 + ka2);
            al[3] = lds_u32(Al + (g + 8) * 256 + ka2);

#pragma unroll
            for (int nt = 0; nt < 4; nt++) {
                const size_t nrow = (size_t)(nw + nt * 8 + g) * HID;
                uint32_t bh0 = ldg_u32(Wh + nrow + kb + 2 * t4);
                uint32_t bh1 = ldg_u32(Wh + nrow + kb + 2 * t4 + 8);
                uint32_t bl0 = ldg_u32(Wl + nrow + kb + 2 * t4);
                uint32_t bl1 = ldg_u32(Wl + nrow + kb + 2 * t4 + 8);
                mma_bf16(acc[nt], ah, bh0, bh1);
                mma_bf16(acc[nt], ah, bl0, bl1);
                mma_bf16(acc[nt], al, bh0, bh1);
            }
        }

        // bias + activation
        float o[4][4];                      // [nt][j]: rows g/g+8, cols +0/+1
#pragma unroll
        for (int nt = 0; nt < 4; nt++) {
            const int c = nw + nt * 8 + 2 * t4;
            const float b0 = bscale * bias[c];
            const float b1 = bscale * bias[c + 1];
            o[nt][0] = acc[nt][0] + b0;
            o[nt][1] = acc[nt][1] + b1;
            o[nt][2] = acc[nt][2] + b0;
            o[nt][3] = acc[nt][3] + b1;
            if (layer == 1) {
#pragma unroll
                for (int j = 0; j < 4; j++) o[nt][j] = fmaxf(o[nt][j], 0.0f);
            }
        }

        if (layer < 2) {
            // write re-split activations back into Ah/Al
            __syncthreads();                // all reads of Ah/Al done
#pragma unroll
            for (int nt = 0; nt < 4; nt++) {
                const int c  = nw + nt * 8 + 2 * t4;
                const int kx = c ^ swz;     // same swizzle for rows g and g+8
                __nv_bfloat16 h, lo;
                split1(o[nt][0], h, lo); Ah[g * 256 + kx] = h;           Al[g * 256 + kx] = lo;
                split1(o[nt][1], h, lo); Ah[g * 256 + kx + 1] = h;       Al[g * 256 + kx + 1] = lo;
                split1(o[nt][2], h, lo); Ah[(g + 8) * 256 + kx] = h;     Al[(g + 8) * 256 + kx] = lo;
                split1(o[nt][3], h, lo); Ah[(g + 8) * 256 + kx + 1] = h; Al[(g + 8) * 256 + kx + 1] = lo;
            }
            __syncthreads();
        } else {
            // final: broadcast to 22 node rows, float2 stores
#pragma unroll
            for (int nt = 0; nt < 4; nt++) {
                const int c = nw + nt * 8 + 2 * t4;
                const float2 v0 = make_float2(o[nt][0], o[nt][1]);
                const float2 v1 = make_float2(o[nt][2], o[nt][3]);
                size_t base0 = ((size_t)(m0 + g) * NNODE) * HID + c;
                size_t base1 = ((size_t)(m0 + g + 8) * NNODE) * HID + c;
#pragma unroll
                for (int p = 0; p < NNODE; p++) {
                    *(float2*)&out[base0 + (size_t)p * HID] = v0;
                    *(float2*)&out[base1 + (size_t)p * HID] = v1;
                }
            }
        }
    }
}

// ---------------------------------------------------------------------------
extern "C" void kernel_launch(void* const* d_in, const int* in_sizes, int n_in,
                              void* d_out, int out_size) {
    const float* x   = (const float*)d_in[0];
    const float* We1 = (const float*)d_in[1];
    const float* be1 = (const float*)d_in[2];
    const float* We2 = (const float*)d_in[3];
    const float* be2 = (const float*)d_in[4];
    const float* Wn1 = (const float*)d_in[5];
    const float* bn1 = (const float*)d_in[6];
    const float* Wn2 = (const float*)d_in[7];
    const float* bn2 = (const float*)d_in[8];
    float* out = (float*)d_out;

    // K1 (+ fused tail-weight transpose/split): -> split hs, split Wt
    k1_mma<<<dim3(4, 67), 256>>>(x, We1, be1, We2, Wn1, Wn2);

    // Barrier-free fused 3-layer tail
    tail_ws<<<32, 256>>>(be2, bn1, bn2, out);
}

// round 11
// speedup vs baseline: 1.8936x; 1.8936x over previous
#include <cuda_runtime.h>
#include <cuda_bf16.h>
#include <cstdint>

#define BSZ   512
#define NNODE 22
#define INDIM 128
#define HID   256
#define MROWS (BSZ * NNODE)   // 11264

// Scratch (device globals) — activations & weights stored pre-split (bf16 hi/lo)
__device__ __nv_bfloat16 g_hsh[BSZ * HID], g_hsl[BSZ * HID];
__device__ __nv_bfloat16 g_Sh [BSZ * HID], g_Sl [BSZ * HID];
__device__ __nv_bfloat16 g_th [BSZ * HID], g_tl [BSZ * HID];
__device__ __nv_bfloat16 g_Wth[3 * HID * HID], g_Wtl[3 * HID * HID]; // [n][k]

// per-row-group arrival counters: cnt[layer][m-group]; zeroed by K1 each replay
__device__ unsigned g_cnt[2][32];

// ---------------------------------------------------------------------------
// bf16 split-2 helpers
// ---------------------------------------------------------------------------
__device__ __forceinline__ void bf16_split2(float v0, float v1,
                                            uint32_t& hi, uint32_t& lo) {
    __nv_bfloat162 h = __float22bfloat162_rn(make_float2(v0, v1));
    float2 hf = __bfloat1622float2(h);
    __nv_bfloat162 l = __float22bfloat162_rn(make_float2(v0 - hf.x, v1 - hf.y));
    hi = *reinterpret_cast<uint32_t*>(&h);
    lo = *reinterpret_cast<uint32_t*>(&l);
}

__device__ __forceinline__ void split1(float v, __nv_bfloat16& h, __nv_bfloat16& l) {
    h = __float2bfloat16_rn(v);
    l = __float2bfloat16_rn(v - __bfloat162float(h));
}

__device__ __forceinline__ void mma_bf16(float* d, const uint32_t* a,
                                         uint32_t b0, uint32_t b1) {
    asm volatile(
        "mma.sync.aligned.m16n8k16.row.col.f32.bf16.bf16.f32 "
        "{%0,%1,%2,%3}, {%4,%5,%6,%7}, {%8,%9}, {%0,%1,%2,%3};"
        : "+f"(d[0]), "+f"(d[1]), "+f"(d[2]), "+f"(d[3])
        : "r"(a[0]), "r"(a[1]), "r"(a[2]), "r"(a[3]), "r"(b0), "r"(b1));
}

__device__ __forceinline__ uint32_t lds_u32(const __nv_bfloat16* p) {
    return *reinterpret_cast<const uint32_t*>(p);
}

// ---------------------------------------------------------------------------
// K1: h = relu(x @ (We1[:128]+We1[128:]) + be1), fused 22-row segment reduce.
// grid (4, 64+3); y>=64 -> weight transpose+split role (+ counter reset).
// ---------------------------------------------------------------------------
__global__ __launch_bounds__(256)
void k1_mma(const float* __restrict__ x,
            const float* __restrict__ We1,
            const float* __restrict__ be1,
            const float* __restrict__ We2,
            const float* __restrict__ Wn1,
            const float* __restrict__ Wn2) {
    if (blockIdx.y >= 64) {
        const int mat = blockIdx.y - 64;
        // reset tail counters for this replay (once)
        if (mat == 0 && blockIdx.x == 0 && threadIdx.x < 64)
            ((unsigned*)g_cnt)[threadIdx.x] = 0u;
        const float* Wsrc = (mat == 0) ? We2 : (mat == 1) ? Wn1 : Wn2;
        __nv_bfloat16* dh = g_Wth + mat * HID * HID;
        __nv_bfloat16* dl = g_Wtl + mat * HID * HID;
        const int k0 = blockIdx.x * 64;
        const int n  = threadIdx.x;
        for (int kq = 0; kq < 64; kq += 4) {
            __nv_bfloat16 h[4], l[4];
#pragma unroll
            for (int i = 0; i < 4; i++)
                split1(Wsrc[(size_t)(k0 + kq + i) * HID + n], h[i], l[i]);
            *(uint2*)&dh[(size_t)n * HID + k0 + kq] = *(uint2*)h;
            *(uint2*)&dl[(size_t)n * HID + k0 + kq] = *(uint2*)l;
        }
        return;
    }

    __shared__ __align__(16) unsigned char sm[176 * 68 * 4];
    __nv_bfloat16* Ah = (__nv_bfloat16*)sm;                    // [176][40]
    __nv_bfloat16* Al = (__nv_bfloat16*)(sm + 14080);
    __nv_bfloat16* Bh = (__nv_bfloat16*)(sm + 28160);          // [64][40]
    __nv_bfloat16* Bl = (__nv_bfloat16*)(sm + 33280);
    float* hb = (float*)sm;                                    // [176][68]

    const int t  = threadIdx.x;
    const int w  = t >> 5;
    const int l  = t & 31;
    const int g  = l >> 2;
    const int t4 = l & 3;
    const int n0 = blockIdx.x * 64;
    const int m0 = blockIdx.y * 176;

    float acc[11][4];
#pragma unroll
    for (int mt = 0; mt < 11; mt++)
#pragma unroll
        for (int j = 0; j < 4; j++) acc[mt][j] = 0.0f;

    for (int kc = 0; kc < 4; kc++) {
        const int k0 = kc * 32;
#pragma unroll
        for (int j = 0; j < 6; j++) {
            int flat = j * 256 + t;
            if (flat < 1408) {
                int m  = flat >> 3;
                int kq = (flat & 7) * 4;
                float4 v = *(const float4*)&x[(size_t)(m0 + m) * INDIM + k0 + kq];
                uint32_t h0, l0, h1, l1;
                bf16_split2(v.x, v.y, h0, l0);
                bf16_split2(v.z, v.w, h1, l1);
                *(uint32_t*)&Ah[m * 40 + kq]     = h0;
                *(uint32_t*)&Ah[m * 40 + kq + 2] = h1;
                *(uint32_t*)&Al[m * 40 + kq]     = l0;
                *(uint32_t*)&Al[m * 40 + kq + 2] = l1;
            }
        }
#pragma unroll
        for (int j = 0; j < 8; j++) {
            int flat = j * 256 + t;
            int kl = flat >> 6;
            int n  = flat & 63;
            float v = We1[(size_t)(k0 + kl) * HID + n0 + n]
                    + We1[(size_t)(k0 + kl + INDIM) * HID + n0 + n];
            split1(v, Bh[n * 40 + kl], Bl[n * 40 + kl]);
        }
        __syncthreads();

#pragma unroll
        for (int ks = 0; ks < 2; ks++) {
            const int kb = ks * 16 + 2 * t4;
            uint32_t bh0 = lds_u32(Bh + (8 * w + g) * 40 + kb);
            uint32_t bh1 = lds_u32(Bh + (8 * w + g) * 40 + kb + 8);
            uint32_t bl0 = lds_u32(Bl + (8 * w + g) * 40 + kb);
            uint32_t bl1 = lds_u32(Bl + (8 * w + g) * 40 + kb + 8);
#pragma unroll
            for (int mt = 0; mt < 11; mt++) {
                const int rb = mt * 16;
                uint32_t ah[4], al[4];
                ah[0] = lds_u32(Ah + (rb + g) * 40 + kb);
                ah[1] = lds_u32(Ah + (rb + g + 8) * 40 + kb);
                ah[2] = lds_u32(Ah + (rb + g) * 40 + kb + 8);
                ah[3] = lds_u32(Ah + (rb + g + 8) * 40 + kb + 8);
                al[0] = lds_u32(Al + (rb + g) * 40 + kb);
                al[1] = lds_u32(Al + (rb + g + 8) * 40 + kb);
                al[2] = lds_u32(Al + (rb + g) * 40 + kb + 8);
                al[3] = lds_u32(Al + (rb + g + 8) * 40 + kb + 8);
                mma_bf16(acc[mt], ah, bh0, bh1);
                mma_bf16(acc[mt], ah, bl0, bl1);
                mma_bf16(acc[mt], al, bh0, bh1);
            }
        }
        __syncthreads();
    }

    const int   cc  = 8 * w + 2 * t4;
    const float bv0 = be1[n0 + cc];
    const float bv1 = be1[n0 + cc + 1];
#pragma unroll
    for (int mt = 0; mt < 11; mt++) {
        const int r0 = mt * 16 + g;
        const int r1 = r0 + 8;
        hb[r0 * 68 + cc]     = fmaxf(acc[mt][0] + bv0, 0.0f);
        hb[r0 * 68 + cc + 1] = fmaxf(acc[mt][1] + bv1, 0.0f);
        hb[r1 * 68 + cc]     = fmaxf(acc[mt][2] + bv0, 0.0f);
        hb[r1 * 68 + cc + 1] = fmaxf(acc[mt][3] + bv1, 0.0f);
    }
    __syncthreads();

    {
        const int c = t & 63;
#pragma unroll
        for (int hh = 0; hh < 2; hh++) {
            const int gg = (t >> 6) + hh * 4;
            float s = 0.0f;
#pragma unroll
            for (int i = 0; i < 22; i++)
                s += hb[(gg * 22 + i) * 68 + c];
            size_t o = (size_t)(blockIdx.y * 8 + gg) * HID + n0 + c;
            split1(s, g_hsh[o], g_hsl[o]);
        }
    }
}

// ---------------------------------------------------------------------------
// One tail layer (identical math to round-8 tail_bf16).
// Block = 16x32 tile, 128 threads, warp split-K (64 each) + smem reduce.
// ---------------------------------------------------------------------------
template <bool RELU, bool BCAST>
__device__ __forceinline__ void tail_layer(
    unsigned char* sm,
    const __nv_bfloat16* __restrict__ Ahg, const __nv_bfloat16* __restrict__ Alg,
    const __nv_bfloat16* __restrict__ Wh,  const __nv_bfloat16* __restrict__ Wl,
    const float* __restrict__ bias, float biasScale,
    float* __restrict__ Cf,
    __nv_bfloat16* __restrict__ Chg, __nv_bfloat16* __restrict__ Clg,
    int m0, int n0) {
    __nv_bfloat16* Ah = (__nv_bfloat16*)sm;             // [16][256]
    __nv_bfloat16* Al = (__nv_bfloat16*)(sm + 8192);
    __nv_bfloat16* Bh = (__nv_bfloat16*)(sm + 16384);   // [32][256]
    __nv_bfloat16* Bl = (__nv_bfloat16*)(sm + 32768);
    typedef float RedT[16][33];
    RedT* red = (RedT*)(sm + 16384);                    // alias Bh (post-sync)

    const int t  = threadIdx.x;
    const int w  = t >> 5;
    const int l  = t & 31;
    const int g  = l >> 2;
    const int t4 = l & 3;

    // ---- stage A [16 x 256] + B^T [32 x 256]: uint4 copies ----
#pragma unroll
    for (int j = 0; j < 4; j++) {
        int flat = j * 128 + t;            // uint4 index over [16][32]
        int m   = flat >> 5;
        int kq8 = (flat & 31) * 8;
        int kx  = kq8 ^ (8 * (m & 7));
        *(uint4*)&Ah[m * 256 + kx] = *(const uint4*)&Ahg[(size_t)(m0 + m) * HID + kq8];
        *(uint4*)&Al[m * 256 + kx] = *(const uint4*)&Alg[(size_t)(m0 + m) * HID + kq8];
    }
#pragma unroll
    for (int j = 0; j < 8; j++) {
        int flat = j * 128 + t;            // uint4 index over [32][32]
        int n   = flat >> 5;
        int kq8 = (flat & 31) * 8;
        int kx  = kq8 ^ (8 * (n & 7));
        *(uint4*)&Bh[n * 256 + kx] = *(const uint4*)&Wh[(size_t)(n0 + n) * HID + kq8];
        *(uint4*)&Bl[n * 256 + kx] = *(const uint4*)&Wl[(size_t)(n0 + n) * HID + kq8];
    }
    __syncthreads();

    float acc[4][4];
#pragma unroll
    for (int nt = 0; nt < 4; nt++)
#pragma unroll
        for (int j = 0; j < 4; j++) acc[nt][j] = 0.0f;

#pragma unroll
    for (int ks = 0; ks < 4; ks++) {
        const int kb  = 64 * w + 16 * ks;
        const int ka0 = (kb + 2 * t4) ^ (8 * g);
        const int ka2 = (kb + 2 * t4 + 8) ^ (8 * g);

        uint32_t ah[4], al[4];
        ah[0] = lds_u32(Ah + g * 256 + ka0);
        ah[1] = lds_u32(Ah + (g + 8) * 256 + ka0);
        ah[2] = lds_u32(Ah + g * 256 + ka2);
        ah[3] = lds_u32(Ah + (g + 8) * 256 + ka2);
        al[0] = lds_u32(Al + g * 256 + ka0);
        al[1] = lds_u32(Al + (g + 8) * 256 + ka0);
        al[2] = lds_u32(Al + g * 256 + ka2);
        al[3] = lds_u32(Al + (g + 8) * 256 + ka2);

#pragma unroll
        for (int nt = 0; nt < 4; nt++) {
            const int n = nt * 8 + g;
            uint32_t bh0 = lds_u32(Bh + n * 256 + ka0);
            uint32_t bh1 = lds_u32(Bh + n * 256 + ka2);
            uint32_t bl0 = lds_u32(Bl + n * 256 + ka0);
            uint32_t bl1 = lds_u32(Bl + n * 256 + ka2);
            mma_bf16(acc[nt], ah, bh0, bh1);
            mma_bf16(acc[nt], ah, bl0, bl1);
            mma_bf16(acc[nt], al, bh0, bh1);
        }
    }
    __syncthreads();

#pragma unroll
    for (int nt = 0; nt < 4; nt++) {
        const int col = nt * 8 + 2 * t4;
        red[w][g][col]         = acc[nt][0];
        red[w][g][col + 1]     = acc[nt][1];
        red[w][g + 8][col]     = acc[nt][2];
        red[w][g + 8][col + 1] = acc[nt][3];
    }
    __syncthreads();

    const int row = t >> 3;
    const int cb  = (t & 7) * 4;
    float v[4];
#pragma unroll
    for (int j = 0; j < 4; j++)
        v[j] = red[0][row][cb + j] + red[1][row][cb + j]
             + red[2][row][cb + j] + red[3][row][cb + j];

    const float4 bv = *(const float4*)&bias[n0 + cb];
    float o[4];
    o[0] = v[0] + biasScale * bv.x;
    o[1] = v[1] + biasScale * bv.y;
    o[2] = v[2] + biasScale * bv.z;
    o[3] = v[3] + biasScale * bv.w;
    if (RELU) {
#pragma unroll
        for (int j = 0; j < 4; j++) o[j] = fmaxf(o[j], 0.0f);
    }

    const int rowg = m0 + row;
    const int colg = n0 + cb;
    if (!BCAST) {
        __nv_bfloat16 h[4], lo[4];
#pragma unroll
        for (int j = 0; j < 4; j++) split1(o[j], h[j], lo[j]);
        *(uint2*)&Chg[(size_t)rowg * HID + colg] = *(uint2*)h;
        *(uint2*)&Clg[(size_t)rowg * HID + colg] = *(uint2*)lo;
    } else {
        float4 ov = make_float4(o[0], o[1], o[2], o[3]);
        size_t base = ((size_t)rowg * NNODE) * HID + colg;
#pragma unroll
        for (int p = 0; p < NNODE; p++)
            *(float4*)&Cf[base + (size_t)p * HID] = ov;
    }
}

// ---------------------------------------------------------------------------
// Row-group dataflow sync: arrive on cnt[l][mg], wait for all 8 producers.
// All 256 blocks co-resident (48KB smem, 128 thr -> 4 blocks/SM, 592 >= 256).
// ---------------------------------------------------------------------------
__device__ __forceinline__ void row_sync(int lyr, int mg) {
    __threadfence();         // publish this thread's tile writes
    __syncthreads();         // all threads of block have published
    if (threadIdx.x == 0) {
        atomicAdd(&g_cnt[lyr][mg], 1u);
        volatile unsigned* c = &g_cnt[lyr][mg];
        while (*c < 8u) { }
        __threadfence();     // acquire: order subsequent loads
    }
    __syncthreads();
}

// ---------------------------------------------------------------------------
// Fused tail: 3 layers in one kernel; sync only within row-groups.
// grid = 256 blocks (bx&7 = n-tile, bx>>3 = m-group), 128 threads, 48KB smem.
// ---------------------------------------------------------------------------
__global__ __launch_bounds__(128)
void tail_fused(const float* __restrict__ be2,
                const float* __restrict__ bn1,
                const float* __restrict__ bn2,
                float* __restrict__ out) {
    __shared__ __align__(16) unsigned char sm[49152];

    const int n0 = (blockIdx.x & 7) * 32;
    const int mg = blockIdx.x >> 3;
    const int m0 = mg * 16;

    // L0: S = hs @ We2 + 22*be2
    tail_layer<false, false>(sm, g_hsh, g_hsl, g_Wth, g_Wtl,
                             be2, (float)NNODE, nullptr, g_Sh, g_Sl, m0, n0);
    row_sync(0, mg);
    // L1: t = relu(S @ Wn1 + bn1)
    tail_layer<true, false>(sm, g_Sh, g_Sl,
                            g_Wth + HID * HID, g_Wtl + HID * HID,
                            bn1, 1.0f, nullptr, g_th, g_tl, m0, n0);
    row_sync(1, mg);
    // L2: out = t @ Wn2 + bn2, broadcast over 22 nodes
    tail_layer<false, true>(sm, g_th, g_tl,
                            g_Wth + 2 * HID * HID, g_Wtl + 2 * HID * HID,
                            bn2, 1.0f, out, nullptr, nullptr, m0, n0);
}

// ---------------------------------------------------------------------------
extern "C" void kernel_launch(void* const* d_in, const int* in_sizes, int n_in,
                              void* d_out, int out_size) {
    const float* x   = (const float*)d_in[0];
    const float* We1 = (const float*)d_in[1];
    const float* be1 = (const float*)d_in[2];
    const float* We2 = (const float*)d_in[3];
    const float* be2 = (const float*)d_in[4];
    const float* Wn1 = (const float*)d_in[5];
    const float* bn1 = (const float*)d_in[6];
    const float* Wn2 = (const float*)d_in[7];
    const float* bn2 = (const float*)d_in[8];
    float* out = (float*)d_out;

    // K1 (+ weight transpose/split + counter reset): -> split hs, split Wt
    k1_mma<<<dim3(4, 67), 256>>>(x, We1, be1, We2, Wn1, Wn2);

    // Fused 3-layer tail with per-row-group dataflow sync
    tail_fused<<<256, 128>>>(be2, bn1, bn2, out);
}